// round 14
// baseline (speedup 1.0000x reference)
#include <cuda_runtime.h>
#include <cuda_bf16.h>
#include <cstdint>
#include <cfloat>

#define HDIM 128
#define MAXGRID 512
#define CANDCAP 32768

// ---------------- device scratch (static, no allocation) ----------------
__device__ float d_G0[HDIM];
__device__ float d_Qm[1000 * HDIM];
__device__ float d_Pj[5000 * HDIM];
__device__ float d_scores[200000];
__device__ float d_bMax[MAXGRID];
__device__ int   d_bArg[MAXGRID];
__device__ float d_bM[MAXGRID];
__device__ float d_bE[MAXGRID];
__device__ float d_bS[MAXGRID];
__device__ int   d_candCount;
__device__ int   d_candList[CANDCAP];
__device__ float d_candScore[CANDCAP];

// ---------------- g0: G0[k] = b0[k] + sum_c xg[c] * W0[c,k] (2-way c-split) ----------------
__global__ void g0_kernel(const float* __restrict__ xg,
                          const float* __restrict__ W0,
                          const float* __restrict__ b0) {
    __shared__ float xs[2 * HDIM];
    __shared__ float part[2 * HDIM];
    int tid = threadIdx.x;            // 0..255
    xs[tid] = xg[tid];
    __syncthreads();
    int k = tid & 127;
    int half = tid >> 7;              // 0 or 1
    float acc = 0.f;
    #pragma unroll 8
    for (int c = half * HDIM; c < (half + 1) * HDIM; c++)
        acc = fmaf(xs[c], W0[c * HDIM + k], acc);
    part[tid] = acc;
    __syncthreads();
    if (tid < HDIM) d_G0[tid] = part[tid] + part[tid + HDIM] + b0[tid];
}

// ---------------- pre kernel: 64 rows/tile, 8 rows/thread ----------------
#define PTR 64      // rows per tile
__global__ void pre_kernel(const float* __restrict__ Xm,
                           const float* __restrict__ Xj,
                           const float* __restrict__ W0,
                           int M, int J, int gQm) {
    extern __shared__ float sm[];
    float* Ws = sm;              // 128x128 = 16384
    float* Xs = sm + 16384;      // 64x128 = 8192
    int tid = threadIdx.x;

    int mode = (blockIdx.x < gQm) ? 0 : 1;
    int tile = (mode == 0) ? blockIdx.x : blockIdx.x - gQm;
    int rows = (mode == 0) ? M : J;
    const float* X  = (mode == 0) ? Xm : Xj;
    const float* Wp = W0 + ((mode == 0) ? 256 : 384) * HDIM;
    float* Out = (mode == 0) ? d_Qm : d_Pj;

    {
        const float4* Wg = (const float4*)Wp;
        float4* Ws4 = (float4*)Ws;
        for (int i = tid; i < 4096; i += 256) Ws4[i] = Wg[i];
    }

    int og = tid >> 5, cg = tid & 31;
    float addv[4];
    #pragma unroll
    for (int u = 0; u < 4; u++)
        addv[u] = (mode == 0) ? d_G0[cg * 4 + u] : 0.0f;

    int base = tile * PTR;
    for (int s = tid; s < PTR * 32; s += 256) {
        int r = s >> 5, c4 = (s & 31) << 2;
        float4 v = make_float4(0.f, 0.f, 0.f, 0.f);
        if (base + r < rows) v = *(const float4*)&X[(base + r) * HDIM + c4];
        *(float4*)&Xs[r * HDIM + c4] = v;
    }
    __syncthreads();

    // 8 rows per thread (rows og*8..og*8+7), 4 cols (cg*4..cg*4+3)
    float acc[8][4];
    #pragma unroll
    for (int o = 0; o < 8; o++)
        #pragma unroll
        for (int u = 0; u < 4; u++) acc[o][u] = 0.0f;

    #pragma unroll 2
    for (int c = 0; c < HDIM; c += 4) {
        float4 a[8];
        #pragma unroll
        for (int o = 0; o < 8; o++)
            a[o] = *(float4*)&Xs[(og * 8 + o) * HDIM + c];
        #pragma unroll
        for (int u = 0; u < 4; u++) {
            float4 w = *(float4*)&Ws[(c + u) * HDIM + cg * 4];
            #pragma unroll
            for (int o = 0; o < 8; o++) {
                float av = (&a[o].x)[u];
                acc[o][0] = fmaf(av, w.x, acc[o][0]);
                acc[o][1] = fmaf(av, w.y, acc[o][1]);
                acc[o][2] = fmaf(av, w.z, acc[o][2]);
                acc[o][3] = fmaf(av, w.w, acc[o][3]);
            }
        }
    }
    #pragma unroll
    for (int o = 0; o < 8; o++) {
        int r = base + og * 8 + o;
        if (r < rows) {
            float4 v;
            v.x = acc[o][0] + addv[0]; v.y = acc[o][1] + addv[1];
            v.z = acc[o][2] + addv[2]; v.w = acc[o][3] + addv[3];
            *(float4*)&Out[r * HDIM + cg * 4] = v;
        }
    }
}

// ============ HMMA main: 32-row tiles, cp.async pipelined, online softmax ============
#define TROWS 32
#define RS 136
#define RAWBUF  32768
#define OFF_AH  (2 * RAWBUF)
#define OFF_AL  (OFF_AH + TROWS * RS * 2)
#define OFF_KX  (OFF_AL + TROWS * RS * 2)
#define KXNG    (32 * 33)
#define OFF_B1S (OFF_KX + 4 * KXNG * 4)
#define OFF_W2S (OFF_B1S + 512)
#define OFF_IDX (OFF_W2S + 512)
#define SMEM_MMA (OFF_IDX + 512 + 256)

__device__ __forceinline__ void mma_bf16(float* d, uint32_t a0, uint32_t a1,
                                         uint32_t a2, uint32_t a3,
                                         uint32_t b0, uint32_t b1) {
    asm volatile(
        "mma.sync.aligned.m16n8k16.row.col.f32.bf16.bf16.f32 "
        "{%0,%1,%2,%3}, {%4,%5,%6,%7}, {%8,%9}, {%0,%1,%2,%3};"
        : "+f"(d[0]), "+f"(d[1]), "+f"(d[2]), "+f"(d[3])
        : "r"(a0), "r"(a1), "r"(a2), "r"(a3), "r"(b0), "r"(b1));
}
__device__ __forceinline__ void ldsm_x4(uint32_t* r, uint32_t saddr) {
    asm volatile("ldmatrix.sync.aligned.m8n8.x4.shared.b16 {%0,%1,%2,%3}, [%4];"
        : "=r"(r[0]), "=r"(r[1]), "=r"(r[2]), "=r"(r[3]) : "r"(saddr));
}
__device__ __forceinline__ uint32_t smem_u32(const void* p) {
    uint32_t a;
    asm("{ .reg .u64 t; cvta.to.shared.u64 t, %1; cvt.u32.u64 %0, t; }" : "=r"(a) : "l"(p));
    return a;
}
__device__ __forceinline__ uint32_t pack_bf16x2(__nv_bfloat16 lo, __nv_bfloat16 hi) {
    __nv_bfloat162 p(lo, hi);
    return *(uint32_t*)&p;
}
__device__ __forceinline__ void cp16(uint32_t dst, const void* src) {
    asm volatile("cp.async.cg.shared.global [%0], [%1], 16;" :: "r"(dst), "l"(src));
}
#define CP_COMMIT() asm volatile("cp.async.commit_group;" ::: "memory")
#define CP_WAIT0()  asm volatile("cp.async.wait_group 0;" ::: "memory")

__device__ __forceinline__ void smx_merge(float& m1, float& e1, float& s1,
                                          float m2, float e2, float s2) {
    if (e2 == 0.f) return;
    if (e1 == 0.f) { m1 = m2; e1 = e2; s1 = s2; return; }
    float m = fmaxf(m1, m2);
    float f1 = expf(m1 - m), f2 = expf(m2 - m);
    s1 = (s1 + (m1 - m) * e1) * f1 + (s2 + (m2 - m) * e2) * f2;
    e1 = e1 * f1 + e2 * f2;
    m1 = m;
}

__global__ void __launch_bounds__(256, 2)
mma_main(const int* __restrict__ m_ids,
         const int* __restrict__ job_idx,
         const float* __restrict__ W1,
         const float* __restrict__ b1,
         const float* __restrict__ W2,
         const float* __restrict__ b2,
         int N) {
    extern __shared__ char smem[];
    uint32_t smemB = smem_u32(smem);
    float* kx   = (float*)(smem + OFF_KX);
    float* b1s  = (float*)(smem + OFF_B1S);
    float* W2s  = (float*)(smem + OFF_W2S);

    int tid = threadIdx.x;
    int wid = tid >> 5;
    int lane = tid & 31;
    int g = lane >> 2;
    int tig = lane & 3;
    int ng = wid & 3;
    int kg = wid >> 2;

    if (tid < HDIM) { b1s[tid] = b1[tid]; W2s[tid] = W2[tid]; }

    uint32_t Bh[4][4][2], Bl[4][4][2];
    #pragma unroll
    for (int nt = 0; nt < 4; nt++) {
        int n = ng * 32 + nt * 8 + g;
        #pragma unroll
        for (int kfi = 0; kfi < 4; kfi++) {
            #pragma unroll
            for (int r = 0; r < 2; r++) {
                int k0 = (kg * 4 + kfi) * 16 + r * 8 + tig * 2;
                float w0 = W1[k0 * HDIM + n];
                float w1 = W1[(k0 + 1) * HDIM + n];
                __nv_bfloat16 h0 = __float2bfloat16_rn(w0);
                __nv_bfloat16 h1 = __float2bfloat16_rn(w1);
                Bh[nt][kfi][r] = pack_bf16x2(h0, h1);
                Bl[nt][kfi][r] = pack_bf16x2(
                    __float2bfloat16_rn(w0 - __bfloat162float(h0)),
                    __float2bfloat16_rn(w1 - __bfloat162float(h1)));
            }
        }
    }

    uint32_t laneByte = (uint32_t)(((lane & 15) * RS + (lane >> 4) * 8) * 2);
    uint32_t AhLane = smemB + OFF_AH + laneByte + (uint32_t)(kg * 64 * 2);
    uint32_t AlLane = smemB + OFF_AL + laneByte + (uint32_t)(kg * 64 * 2);

    int ntiles = (N + TROWS - 1) / TROWS;
    int stride = gridDim.x;

    float tBest = -FLT_MAX;
    int   tArg  = 0x7FFFFFFF;
    float wBest = -FLT_MAX;
    float mloc = -FLT_MAX, seL = 0.f, ssL = 0.f;

    #pragma unroll
    for (int s = 0; s < 2; s++) {
        int ts = blockIdx.x + s * stride;
        if (tid < 64 && ts < ntiles) {
            int r = tid & 31;
            int op = ts * TROWS + r; if (op >= N) op = N - 1;
            int v = (tid < 32) ? m_ids[op] : job_idx[op];
            *((int*)(smem + OFF_IDX + s * 256) + ((tid < 32) ? 0 : 32) + r) = v;
        }
    }
    __syncthreads();
    if (blockIdx.x < ntiles) {
        int* im = (int*)(smem + OFF_IDX);
        int* ij = im + 32;
        #pragma unroll
        for (int k = 0; k < 4; k++) {
            int chunk = tid + k * 256;
            int row = chunk >> 5, seg = chunk & 31;
            cp16(smemB + row * 512 + seg * 16, d_Qm + im[row] * HDIM + seg * 4);
            cp16(smemB + 16384 + row * 512 + seg * 16, d_Pj + ij[row] * HDIM + seg * 4);
        }
    }
    CP_COMMIT();

    int i = 0;
    for (int tile = blockIdx.x; tile < ntiles; i++, tile += stride) {
        int b = i & 1;
        int rawOff = b * RAWBUF;

        CP_WAIT0();
        __syncthreads();

        {
            float* rq = (float*)(smem + rawOff);
            float* rp = (float*)(smem + rawOff + 16384);
            __nv_bfloat16* Ahp = (__nv_bfloat16*)(smem + OFF_AH);
            #pragma unroll
            for (int it = 0; it < 4; it++) {
                int row = wid * 4 + it;
                float4 q = *(float4*)&rq[row * 128 + lane * 4];
                float4 p = *(float4*)&rp[row * 128 + lane * 4];
                float h0 = fmaxf(q.x + p.x, 0.f);
                float h1 = fmaxf(q.y + p.y, 0.f);
                float h2 = fmaxf(q.z + p.z, 0.f);
                float h3 = fmaxf(q.w + p.w, 0.f);
                __nv_bfloat16 a0 = __float2bfloat16_rn(h0);
                __nv_bfloat16 a1 = __float2bfloat16_rn(h1);
                __nv_bfloat16 a2 = __float2bfloat16_rn(h2);
                __nv_bfloat16 a3 = __float2bfloat16_rn(h3);
                uint2 hv, lv;
                hv.x = pack_bf16x2(a0, a1);
                hv.y = pack_bf16x2(a2, a3);
                lv.x = pack_bf16x2(__float2bfloat16_rn(h0 - __bfloat162float(a0)),
                                   __float2bfloat16_rn(h1 - __bfloat162float(a1)));
                lv.y = pack_bf16x2(__float2bfloat16_rn(h2 - __bfloat162float(a2)),
                                   __float2bfloat16_rn(h3 - __bfloat162float(a3)));
                *(uint2*)&Ahp[row * RS + lane * 4] = hv;
                *(uint2*)((char*)&Ahp[row * RS + lane * 4] + (OFF_AL - OFF_AH)) = lv;
            }
        }
        int pfv = 0;
        int t2 = tile + 2 * stride;
        bool hp = (t2 < ntiles) && (tid < 64);
        if (hp) {
            int r = tid & 31;
            int op = t2 * TROWS + r; if (op >= N) op = N - 1;
            pfv = (tid < 32) ? m_ids[op] : job_idx[op];
        }
        __syncthreads();

        if (tile + stride < ntiles) {
            int slot1 = (i + 1) & 1;
            int* im = (int*)(smem + OFF_IDX + slot1 * 256);
            int* ij = im + 32;
            uint32_t dstQ = smemB + (b ^ 1) * RAWBUF;
            #pragma unroll
            for (int k = 0; k < 4; k++) {
                int chunk = tid + k * 256;
                int row = chunk >> 5, seg = chunk & 31;
                cp16(dstQ + row * 512 + seg * 16, d_Qm + im[row] * HDIM + seg * 4);
                cp16(dstQ + 16384 + row * 512 + seg * 16, d_Pj + ij[row] * HDIM + seg * 4);
            }
        }
        CP_COMMIT();
        if (hp) {
            int r = tid & 31;
            *((int*)(smem + OFF_IDX + (i & 1) * 256) + ((tid < 32) ? 0 : 32) + r) = pfv;
        }

        float acc[2][4][4];
        #pragma unroll
        for (int mt = 0; mt < 2; mt++)
            #pragma unroll
            for (int nt = 0; nt < 4; nt++)
                #pragma unroll
                for (int e = 0; e < 4; e++) acc[mt][nt][e] = 0.f;

        #pragma unroll
        for (int kfi = 0; kfi < 4; kfi++) {
            uint32_t kOff = (uint32_t)(kfi * 32);
            #pragma unroll
            for (int mt = 0; mt < 2; mt++) {
                uint32_t rOff = (uint32_t)(mt * 16 * RS * 2) + kOff;
                uint32_t ah[4], al[4];
                ldsm_x4(ah, AhLane + rOff);
                ldsm_x4(al, AlLane + rOff);
                #pragma unroll
                for (int nt = 0; nt < 4; nt++) {
                    mma_bf16(acc[mt][nt], ah[0], ah[1], ah[2], ah[3], Bh[nt][kfi][0], Bh[nt][kfi][1]);
                    mma_bf16(acc[mt][nt], ah[0], ah[1], ah[2], ah[3], Bl[nt][kfi][0], Bl[nt][kfi][1]);
                    mma_bf16(acc[mt][nt], al[0], al[1], al[2], al[3], Bh[nt][kfi][0], Bh[nt][kfi][1]);
                }
            }
        }

        if (kg == 1) {
            float* kxb = kx + ng * KXNG;
            #pragma unroll
            for (int mt = 0; mt < 2; mt++)
                #pragma unroll
                for (int nt = 0; nt < 4; nt++)
                    #pragma unroll
                    for (int e = 0; e < 4; e++) {
                        int row = mt * 16 + g + (e >> 1) * 8;
                        int col = nt * 8 + tig * 2 + (e & 1);
                        kxb[row * 33 + col] = acc[mt][nt][e];
                    }
        }
        __syncthreads();
        if (kg == 0) {
            float* kxb = kx + ng * KXNG;
            #pragma unroll
            for (int mt = 0; mt < 2; mt++) {
                float p0 = 0.f, p1 = 0.f;
                #pragma unroll
                for (int nt = 0; nt < 4; nt++) {
                    int n0 = ng * 32 + nt * 8 + tig * 2;
                    float bb0 = b1s[n0], bb1 = b1s[n0 + 1];
                    float ww0 = W2s[n0], ww1 = W2s[n0 + 1];
                    int r0 = mt * 16 + g, r1 = r0 + 8;
                    int c0 = nt * 8 + tig * 2;
                    float v0 = acc[mt][nt][0] + kxb[r0 * 33 + c0];
                    float v1 = acc[mt][nt][1] + kxb[r0 * 33 + c0 + 1];
                    float v2 = acc[mt][nt][2] + kxb[r1 * 33 + c0];
                    float v3 = acc[mt][nt][3] + kxb[r1 * 33 + c0 + 1];
                    p0 = fmaf(fmaxf(v0 + bb0, 0.f), ww0, p0);
                    p0 = fmaf(fmaxf(v1 + bb1, 0.f), ww1, p0);
                    p1 = fmaf(fmaxf(v2 + bb0, 0.f), ww0, p1);
                    p1 = fmaf(fmaxf(v3 + bb1, 0.f), ww1, p1);
                }
                p0 += __shfl_xor_sync(0xFFFFFFFFu, p0, 1);
                p0 += __shfl_xor_sync(0xFFFFFFFFu, p0, 2);
                p1 += __shfl_xor_sync(0xFFFFFFFFu, p1, 1);
                p1 += __shfl_xor_sync(0xFFFFFFFFu, p1, 2);
                if (tig == 0) {
                    kxb[(mt * 16 + g) * 33 + 32] = p0;
                    kxb[(mt * 16 + g + 8) * 33 + 32] = p1;
                }
            }
        }
        __syncthreads();

        if (tid < TROWS) {
            float s = b2[0];
            #pragma unroll
            for (int n4 = 0; n4 < 4; n4++) s += kx[n4 * KXNG + tid * 33 + 32];
            int op = tile * TROWS + tid;
            bool valid = (op < N);
            float sv = valid ? s : -FLT_MAX;

            float tmax = sv;
            #pragma unroll
            for (int off = 16; off > 0; off >>= 1)
                tmax = fmaxf(tmax, __shfl_xor_sync(0xFFFFFFFFu, tmax, off));
            wBest = fmaxf(wBest, tmax);

            if (valid) {
                d_scores[op] = s;
                if (s >= wBest - 1e-3f) {
                    int p = atomicAdd(&d_candCount, 1);
                    if (p < CANDCAP) { d_candList[p] = op; d_candScore[p] = s; }
                }
                if (s > tBest || (s == tBest && op < tArg)) { tBest = s; tArg = op; }
                if (s > mloc) {
                    float f = expf(mloc - s);
                    ssL = f * ssL + (mloc - s) * f * seL;
                    seL = f * seL + 1.f;
                    mloc = s;
                } else {
                    float e = expf(s - mloc);
                    seL += e;
                    ssL = fmaf(s - mloc, e, ssL);
                }
            }
        }
        __syncthreads();
    }

    if (tid < 32) {
        #pragma unroll
        for (int off = 16; off > 0; off >>= 1) {
            float ov = __shfl_xor_sync(0xFFFFFFFFu, tBest, off);
            int   oi = __shfl_xor_sync(0xFFFFFFFFu, tArg, off);
            if (ov > tBest || (ov == tBest && oi < tArg)) { tBest = ov; tArg = oi; }
            float om = __shfl_xor_sync(0xFFFFFFFFu, mloc, off);
            float oe = __shfl_xor_sync(0xFFFFFFFFu, seL, off);
            float os = __shfl_xor_sync(0xFFFFFFFFu, ssL, off);
            smx_merge(mloc, seL, ssL, om, oe, os);
        }
        if (lane == 0) {
            d_bMax[blockIdx.x] = tBest;
            d_bArg[blockIdx.x] = tArg;
            d_bM[blockIdx.x] = mloc;
            d_bE[blockIdx.x] = seL;
            d_bS[blockIdx.x] = ssL;
        }
    }
}

// ---------------- fused combine + refine + finalize ----------------
__global__ void combine_refine(const int* __restrict__ m_ids,
                               const int* __restrict__ job_idx,
                               const float* __restrict__ W1,
                               const float* __restrict__ b1,
                               const float* __restrict__ W2,
                               const float* __restrict__ b2,
                               float* __restrict__ out, int nparts) {
    __shared__ float sv[256]; __shared__ int si[256];
    __shared__ float smm[256], sE[256], sS[256];
    __shared__ float gMaxS, gES, gSS;
    __shared__ int scnt;
    __shared__ int slist[64];
    __shared__ float h0[128];
    __shared__ float red[128];
    __shared__ float bestS;
    __shared__ int bestI;
    int tid = threadIdx.x;

    float bv = -FLT_MAX; int bi = 0x7FFFFFFF;
    float m = -FLT_MAX, e = 0.f, s = 0.f;
    for (int i = tid; i < nparts; i += 256) {
        float v = d_bMax[i]; int ix = d_bArg[i];
        if (v > bv || (v == bv && ix < bi)) { bv = v; bi = ix; }
        smx_merge(m, e, s, d_bM[i], d_bE[i], d_bS[i]);
    }
    sv[tid] = bv; si[tid] = bi; smm[tid] = m; sE[tid] = e; sS[tid] = s;
    __syncthreads();
    for (int st = 128; st > 0; st >>= 1) {
        if (tid < st) {
            float v = sv[tid + st]; int ix = si[tid + st];
            if (v > sv[tid] || (v == sv[tid] && ix < si[tid])) { sv[tid] = v; si[tid] = ix; }
            float m1 = smm[tid], e1 = sE[tid], s1 = sS[tid];
            smx_merge(m1, e1, s1, smm[tid + st], sE[tid + st], sS[tid + st]);
            smm[tid] = m1; sE[tid] = e1; sS[tid] = s1;
        }
        __syncthreads();
    }
    if (tid == 0) {
        gMaxS = sv[0]; gES = sE[0]; gSS = sS[0];
        scnt = 0; bestS = -FLT_MAX; bestI = si[0];
    }
    __syncthreads();

    int cnt = d_candCount;
    if (cnt > CANDCAP) cnt = CANDCAP;
    float thr = gMaxS - 1e-3f;
    for (int c = tid; c < cnt; c += 256) {
        float sc = d_candScore[c];
        if (sc >= thr) {
            int p = atomicAdd(&scnt, 1);
            if (p < 64) slist[p] = d_candList[c];
        }
    }
    __syncthreads();
    int nfin = scnt; if (nfin > 64) nfin = 64;

    for (int c = 0; c < nfin; c++) {
        int op = slist[c];
        if (tid < 128) {
            int mm = m_ids[op], jj = job_idx[op];
            h0[tid] = fmaxf(d_Qm[mm * HDIM + tid] + d_Pj[jj * HDIM + tid], 0.f);
        }
        __syncthreads();
        if (tid < 128) {
            float a = b1[tid];
            #pragma unroll 8
            for (int k = 0; k < HDIM; k++)
                a = fmaf(h0[k], W1[k * HDIM + tid], a);
            red[tid] = fmaxf(a, 0.f) * W2[tid];
        }
        __syncthreads();
        for (int st = 64; st > 0; st >>= 1) {
            if (tid < st && tid + st < 128) red[tid] += red[tid + st];
            __syncthreads();
        }
        if (tid == 0) {
            float sx = red[0] + b2[0];
            if (sx > bestS || (sx == bestS && op < bestI)) { bestS = sx; bestI = op; }
        }
        __syncthreads();
    }

    if (tid == 0) {
        float Z = gES, S = gSS;
        float mx = gMaxS;
        int arg = bestI;
        float logZ = logf(Z);
        float lp = (d_scores[arg] - mx) - logZ;
        out[0] = (float)arg;
        out[1] = expf(lp);
        out[2] = lp;
        out[3] = logZ - S / Z;
        d_candCount = 0;
    }
}

// ---------------- launch ----------------
extern "C" void kernel_launch(void* const* d_in, const int* in_sizes, int n_in,
                              void* d_out, int out_size) {
    const float* xg    = (const float*)d_in[0];
    const float* xm    = (const float*)d_in[1];
    const float* xjob  = (const float*)d_in[2];
    const int*   m_ids = (const int*)d_in[3];
    const int*   jidx  = (const int*)d_in[4];
    const float* W0    = (const float*)d_in[5];
    const float* b0    = (const float*)d_in[6];
    const float* W1    = (const float*)d_in[7];
    const float* b1    = (const float*)d_in[8];
    const float* W2    = (const float*)d_in[9];
    const float* b2    = (const float*)d_in[10];

    int M = in_sizes[1] / HDIM;
    int J = in_sizes[2] / HDIM;
    int N = in_sizes[3];

    const int SMEM_PRE = (16384 + PTR * 128) * 4;
    cudaFuncSetAttribute(pre_kernel, cudaFuncAttributeMaxDynamicSharedMemorySize, SMEM_PRE);
    cudaFuncSetAttribute(mma_main,   cudaFuncAttributeMaxDynamicSharedMemorySize, SMEM_MMA);

    g0_kernel<<<1, 256>>>(xg, W0, b0);

    int gQm = (M + PTR - 1) / PTR;
    int gPj = (J + PTR - 1) / PTR;
    pre_kernel<<<gQm + gPj, 256, SMEM_PRE>>>(xm, xjob, W0, M, J, gQm);

    const int GRID_MAIN = 304;
    mma_main<<<GRID_MAIN, 256, SMEM_MMA>>>(m_ids, jidx, W1, b1, W2, b2, N);

    combine_refine<<<1, 256>>>(m_ids, jidx, W1, b1, W2, b2, (float*)d_out, GRID_MAIN);
}

// round 15
// speedup vs baseline: 1.0226x; 1.0226x over previous
#include <cuda_runtime.h>
#include <cuda_bf16.h>
#include <cstdint>
#include <cfloat>

#define HDIM 128
#define MAXGRID 512
#define CANDCAP 32768

// ---------------- device scratch (static, no allocation) ----------------
__device__ float d_G0[HDIM];
__device__ float d_Qm[1000 * HDIM];
__device__ float d_Pj[5000 * HDIM];
__device__ float d_scores[200000];
__device__ float d_bMax[MAXGRID];
__device__ int   d_bArg[MAXGRID];
__device__ float d_bM[MAXGRID];
__device__ float d_bE[MAXGRID];
__device__ float d_bS[MAXGRID];
__device__ int   d_candCount;
__device__ int   d_candList[CANDCAP];
__device__ float d_candScore[CANDCAP];

// ---------------- g0: G0[k] = b0[k] + sum_c xg[c] * W0[c,k] (2-way c-split) ----------------
__global__ void g0_kernel(const float* __restrict__ xg,
                          const float* __restrict__ W0,
                          const float* __restrict__ b0) {
    __shared__ float xs[2 * HDIM];
    __shared__ float part[2 * HDIM];
    int tid = threadIdx.x;            // 0..255
    xs[tid] = xg[tid];
    __syncthreads();
    int k = tid & 127;
    int half = tid >> 7;              // 0 or 1
    float acc = 0.f;
    #pragma unroll 8
    for (int c = half * HDIM; c < (half + 1) * HDIM; c++)
        acc = fmaf(xs[c], W0[c * HDIM + k], acc);
    part[tid] = acc;
    __syncthreads();
    if (tid < HDIM) d_G0[tid] = part[tid] + part[tid + HDIM] + b0[tid];
}

// ---------------- pre kernel: 64 rows/tile, 8 rows/thread ----------------
#define PTR 64      // rows per tile
__global__ void pre_kernel(const float* __restrict__ Xm,
                           const float* __restrict__ Xj,
                           const float* __restrict__ W0,
                           int M, int J, int gQm) {
    extern __shared__ float sm[];
    float* Ws = sm;              // 128x128 = 16384
    float* Xs = sm + 16384;      // 64x128 = 8192
    int tid = threadIdx.x;

    int mode = (blockIdx.x < gQm) ? 0 : 1;
    int tile = (mode == 0) ? blockIdx.x : blockIdx.x - gQm;
    int rows = (mode == 0) ? M : J;
    const float* X  = (mode == 0) ? Xm : Xj;
    const float* Wp = W0 + ((mode == 0) ? 256 : 384) * HDIM;
    float* Out = (mode == 0) ? d_Qm : d_Pj;

    {
        const float4* Wg = (const float4*)Wp;
        float4* Ws4 = (float4*)Ws;
        for (int i = tid; i < 4096; i += 256) Ws4[i] = Wg[i];
    }

    int og = tid >> 5, cg = tid & 31;
    float addv[4];
    #pragma unroll
    for (int u = 0; u < 4; u++)
        addv[u] = (mode == 0) ? d_G0[cg * 4 + u] : 0.0f;

    int base = tile * PTR;
    for (int s = tid; s < PTR * 32; s += 256) {
        int r = s >> 5, c4 = (s & 31) << 2;
        float4 v = make_float4(0.f, 0.f, 0.f, 0.f);
        if (base + r < rows) v = *(const float4*)&X[(base + r) * HDIM + c4];
        *(float4*)&Xs[r * HDIM + c4] = v;
    }
    __syncthreads();

    float acc[8][4];
    #pragma unroll
    for (int o = 0; o < 8; o++)
        #pragma unroll
        for (int u = 0; u < 4; u++) acc[o][u] = 0.0f;

    #pragma unroll 2
    for (int c = 0; c < HDIM; c += 4) {
        float4 a[8];
        #pragma unroll
        for (int o = 0; o < 8; o++)
            a[o] = *(float4*)&Xs[(og * 8 + o) * HDIM + c];
        #pragma unroll
        for (int u = 0; u < 4; u++) {
            float4 w = *(float4*)&Ws[(c + u) * HDIM + cg * 4];
            #pragma unroll
            for (int o = 0; o < 8; o++) {
                float av = (&a[o].x)[u];
                acc[o][0] = fmaf(av, w.x, acc[o][0]);
                acc[o][1] = fmaf(av, w.y, acc[o][1]);
                acc[o][2] = fmaf(av, w.z, acc[o][2]);
                acc[o][3] = fmaf(av, w.w, acc[o][3]);
            }
        }
    }
    #pragma unroll
    for (int o = 0; o < 8; o++) {
        int r = base + og * 8 + o;
        if (r < rows) {
            float4 v;
            v.x = acc[o][0] + addv[0]; v.y = acc[o][1] + addv[1];
            v.z = acc[o][2] + addv[2]; v.w = acc[o][3] + addv[3];
            *(float4*)&Out[r * HDIM + cg * 4] = v;
        }
    }
}

// ============ HMMA main: 32-row tiles, cp.async pipelined, online softmax ============
#define TROWS 32
#define RS 136
#define RAWBUF  32768
#define OFF_AH  (2 * RAWBUF)
#define OFF_AL  (OFF_AH + TROWS * RS * 2)
#define OFF_KX  (OFF_AL + TROWS * RS * 2)
#define KXNG    (32 * 33)
#define OFF_B1S (OFF_KX + 4 * KXNG * 4)
#define OFF_W2S (OFF_B1S + 512)
#define OFF_IDX (OFF_W2S + 512)
#define SMEM_MMA (OFF_IDX + 512 + 256)

__device__ __forceinline__ void mma_bf16(float* d, uint32_t a0, uint32_t a1,
                                         uint32_t a2, uint32_t a3,
                                         uint32_t b0, uint32_t b1) {
    asm volatile(
        "mma.sync.aligned.m16n8k16.row.col.f32.bf16.bf16.f32 "
        "{%0,%1,%2,%3}, {%4,%5,%6,%7}, {%8,%9}, {%0,%1,%2,%3};"
        : "+f"(d[0]), "+f"(d[1]), "+f"(d[2]), "+f"(d[3])
        : "r"(a0), "r"(a1), "r"(a2), "r"(a3), "r"(b0), "r"(b1));
}
__device__ __forceinline__ void ldsm_x4(uint32_t* r, uint32_t saddr) {
    asm volatile("ldmatrix.sync.aligned.m8n8.x4.shared.b16 {%0,%1,%2,%3}, [%4];"
        : "=r"(r[0]), "=r"(r[1]), "=r"(r[2]), "=r"(r[3]) : "r"(saddr));
}
__device__ __forceinline__ uint32_t smem_u32(const void* p) {
    uint32_t a;
    asm("{ .reg .u64 t; cvta.to.shared.u64 t, %1; cvt.u32.u64 %0, t; }" : "=r"(a) : "l"(p));
    return a;
}
__device__ __forceinline__ uint32_t pack_bf16x2(__nv_bfloat16 lo, __nv_bfloat16 hi) {
    __nv_bfloat162 p(lo, hi);
    return *(uint32_t*)&p;
}
__device__ __forceinline__ void cp16(uint32_t dst, const void* src) {
    asm volatile("cp.async.cg.shared.global [%0], [%1], 16;" :: "r"(dst), "l"(src));
}
#define CP_COMMIT() asm volatile("cp.async.commit_group;" ::: "memory")
#define CP_WAIT0()  asm volatile("cp.async.wait_group 0;" ::: "memory")

__device__ __forceinline__ void smx_merge(float& m1, float& e1, float& s1,
                                          float m2, float e2, float s2) {
    if (e2 == 0.f) return;
    if (e1 == 0.f) { m1 = m2; e1 = e2; s1 = s2; return; }
    float m = fmaxf(m1, m2);
    float f1 = expf(m1 - m), f2 = expf(m2 - m);
    s1 = (s1 + (m1 - m) * e1) * f1 + (s2 + (m2 - m) * e2) * f2;
    e1 = e1 * f1 + e2 * f2;
    m1 = m;
}

__global__ void __launch_bounds__(256, 2)
mma_main(const int* __restrict__ m_ids,
         const int* __restrict__ job_idx,
         const float* __restrict__ W1,
         const float* __restrict__ b1,
         const float* __restrict__ W2,
         const float* __restrict__ b2,
         int N) {
    extern __shared__ char smem[];
    uint32_t smemB = smem_u32(smem);
    float* kx   = (float*)(smem + OFF_KX);
    float* b1s  = (float*)(smem + OFF_B1S);
    float* W2s  = (float*)(smem + OFF_W2S);

    int tid = threadIdx.x;
    int wid = tid >> 5;
    int lane = tid & 31;
    int g = lane >> 2;
    int tig = lane & 3;
    int ng = wid & 3;
    int kg = wid >> 2;

    if (tid < HDIM) { b1s[tid] = b1[tid]; W2s[tid] = W2[tid]; }

    uint32_t Bh[4][4][2], Bl[4][4][2];
    #pragma unroll
    for (int nt = 0; nt < 4; nt++) {
        int n = ng * 32 + nt * 8 + g;
        #pragma unroll
        for (int kfi = 0; kfi < 4; kfi++) {
            #pragma unroll
            for (int r = 0; r < 2; r++) {
                int k0 = (kg * 4 + kfi) * 16 + r * 8 + tig * 2;
                float w0 = W1[k0 * HDIM + n];
                float w1 = W1[(k0 + 1) * HDIM + n];
                __nv_bfloat16 h0 = __float2bfloat16_rn(w0);
                __nv_bfloat16 h1 = __float2bfloat16_rn(w1);
                Bh[nt][kfi][r] = pack_bf16x2(h0, h1);
                Bl[nt][kfi][r] = pack_bf16x2(
                    __float2bfloat16_rn(w0 - __bfloat162float(h0)),
                    __float2bfloat16_rn(w1 - __bfloat162float(h1)));
            }
        }
    }

    uint32_t laneByte = (uint32_t)(((lane & 15) * RS + (lane >> 4) * 8) * 2);
    uint32_t AhLane = smemB + OFF_AH + laneByte + (uint32_t)(kg * 64 * 2);
    uint32_t AlLane = smemB + OFF_AL + laneByte + (uint32_t)(kg * 64 * 2);

    int ntiles = (N + TROWS - 1) / TROWS;
    int stride = gridDim.x;

    float tBest = -FLT_MAX;
    int   tArg  = 0x7FFFFFFF;
    float wBest = -FLT_MAX;
    float mloc = -FLT_MAX, seL = 0.f, ssL = 0.f;

    #pragma unroll
    for (int s = 0; s < 2; s++) {
        int ts = blockIdx.x + s * stride;
        if (tid < 64 && ts < ntiles) {
            int r = tid & 31;
            int op = ts * TROWS + r; if (op >= N) op = N - 1;
            int v = (tid < 32) ? m_ids[op] : job_idx[op];
            *((int*)(smem + OFF_IDX + s * 256) + ((tid < 32) ? 0 : 32) + r) = v;
        }
    }
    __syncthreads();
    if (blockIdx.x < ntiles) {
        int* im = (int*)(smem + OFF_IDX);
        int* ij = im + 32;
        #pragma unroll
        for (int k = 0; k < 4; k++) {
            int chunk = tid + k * 256;
            int row = chunk >> 5, seg = chunk & 31;
            cp16(smemB + row * 512 + seg * 16, d_Qm + im[row] * HDIM + seg * 4);
            cp16(smemB + 16384 + row * 512 + seg * 16, d_Pj + ij[row] * HDIM + seg * 4);
        }
    }
    CP_COMMIT();

    int i = 0;
    for (int tile = blockIdx.x; tile < ntiles; i++, tile += stride) {
        int b = i & 1;
        int rawOff = b * RAWBUF;

        CP_WAIT0();
        __syncthreads();

        {
            float* rq = (float*)(smem + rawOff);
            float* rp = (float*)(smem + rawOff + 16384);
            __nv_bfloat16* Ahp = (__nv_bfloat16*)(smem + OFF_AH);
            #pragma unroll
            for (int it = 0; it < 4; it++) {
                int row = wid * 4 + it;
                float4 q = *(float4*)&rq[row * 128 + lane * 4];
                float4 p = *(float4*)&rp[row * 128 + lane * 4];
                float h0 = fmaxf(q.x + p.x, 0.f);
                float h1 = fmaxf(q.y + p.y, 0.f);
                float h2 = fmaxf(q.z + p.z, 0.f);
                float h3 = fmaxf(q.w + p.w, 0.f);
                __nv_bfloat16 a0 = __float2bfloat16_rn(h0);
                __nv_bfloat16 a1 = __float2bfloat16_rn(h1);
                __nv_bfloat16 a2 = __float2bfloat16_rn(h2);
                __nv_bfloat16 a3 = __float2bfloat16_rn(h3);
                uint2 hv, lv;
                hv.x = pack_bf16x2(a0, a1);
                hv.y = pack_bf16x2(a2, a3);
                lv.x = pack_bf16x2(__float2bfloat16_rn(h0 - __bfloat162float(a0)),
                                   __float2bfloat16_rn(h1 - __bfloat162float(a1)));
                lv.y = pack_bf16x2(__float2bfloat16_rn(h2 - __bfloat162float(a2)),
                                   __float2bfloat16_rn(h3 - __bfloat162float(a3)));
                *(uint2*)&Ahp[row * RS + lane * 4] = hv;
                *(uint2*)((char*)&Ahp[row * RS + lane * 4] + (OFF_AL - OFF_AH)) = lv;
            }
        }
        int pfv = 0;
        int t2 = tile + 2 * stride;
        bool hp = (t2 < ntiles) && (tid < 64);
        if (hp) {
            int r = tid & 31;
            int op = t2 * TROWS + r; if (op >= N) op = N - 1;
            pfv = (tid < 32) ? m_ids[op] : job_idx[op];
        }
        __syncthreads();

        if (tile + stride < ntiles) {
            int slot1 = (i + 1) & 1;
            int* im = (int*)(smem + OFF_IDX + slot1 * 256);
            int* ij = im + 32;
            uint32_t dstQ = smemB + (b ^ 1) * RAWBUF;
            #pragma unroll
            for (int k = 0; k < 4; k++) {
                int chunk = tid + k * 256;
                int row = chunk >> 5, seg = chunk & 31;
                cp16(dstQ + row * 512 + seg * 16, d_Qm + im[row] * HDIM + seg * 4);
                cp16(dstQ + 16384 + row * 512 + seg * 16, d_Pj + ij[row] * HDIM + seg * 4);
            }
        }
        CP_COMMIT();
        if (hp) {
            int r = tid & 31;
            *((int*)(smem + OFF_IDX + (i & 1) * 256) + ((tid < 32) ? 0 : 32) + r) = pfv;
        }

        float acc[2][4][4];
        #pragma unroll
        for (int mt = 0; mt < 2; mt++)
            #pragma unroll
            for (int nt = 0; nt < 4; nt++)
                #pragma unroll
                for (int e = 0; e < 4; e++) acc[mt][nt][e] = 0.f;

        #pragma unroll
        for (int kfi = 0; kfi < 4; kfi++) {
            uint32_t kOff = (uint32_t)(kfi * 32);
            #pragma unroll
            for (int mt = 0; mt < 2; mt++) {
                uint32_t rOff = (uint32_t)(mt * 16 * RS * 2) + kOff;
                uint32_t ah[4], al[4];
                ldsm_x4(ah, AhLane + rOff);
                ldsm_x4(al, AlLane + rOff);
                #pragma unroll
                for (int nt = 0; nt < 4; nt++) {
                    mma_bf16(acc[mt][nt], ah[0], ah[1], ah[2], ah[3], Bh[nt][kfi][0], Bh[nt][kfi][1]);
                    mma_bf16(acc[mt][nt], ah[0], ah[1], ah[2], ah[3], Bl[nt][kfi][0], Bl[nt][kfi][1]);
                    mma_bf16(acc[mt][nt], al[0], al[1], al[2], al[3], Bh[nt][kfi][0], Bh[nt][kfi][1]);
                }
            }
        }

        if (kg == 1) {
            float* kxb = kx + ng * KXNG;
            #pragma unroll
            for (int mt = 0; mt < 2; mt++)
                #pragma unroll
                for (int nt = 0; nt < 4; nt++)
                    #pragma unroll
                    for (int e = 0; e < 4; e++) {
                        int row = mt * 16 + g + (e >> 1) * 8;
                        int col = nt * 8 + tig * 2 + (e & 1);
                        kxb[row * 33 + col] = acc[mt][nt][e];
                    }
        }
        __syncthreads();
        if (kg == 0) {
            float* kxb = kx + ng * KXNG;
            #pragma unroll
            for (int mt = 0; mt < 2; mt++) {
                float p0 = 0.f, p1 = 0.f;
                #pragma unroll
                for (int nt = 0; nt < 4; nt++) {
                    int n0 = ng * 32 + nt * 8 + tig * 2;
                    float bb0 = b1s[n0], bb1 = b1s[n0 + 1];
                    float ww0 = W2s[n0], ww1 = W2s[n0 + 1];
                    int r0 = mt * 16 + g, r1 = r0 + 8;
                    int c0 = nt * 8 + tig * 2;
                    float v0 = acc[mt][nt][0] + kxb[r0 * 33 + c0];
                    float v1 = acc[mt][nt][1] + kxb[r0 * 33 + c0 + 1];
                    float v2 = acc[mt][nt][2] + kxb[r1 * 33 + c0];
                    float v3 = acc[mt][nt][3] + kxb[r1 * 33 + c0 + 1];
                    p0 = fmaf(fmaxf(v0 + bb0, 0.f), ww0, p0);
                    p0 = fmaf(fmaxf(v1 + bb1, 0.f), ww1, p0);
                    p1 = fmaf(fmaxf(v2 + bb0, 0.f), ww0, p1);
                    p1 = fmaf(fmaxf(v3 + bb1, 0.f), ww1, p1);
                }
                p0 += __shfl_xor_sync(0xFFFFFFFFu, p0, 1);
                p0 += __shfl_xor_sync(0xFFFFFFFFu, p0, 2);
                p1 += __shfl_xor_sync(0xFFFFFFFFu, p1, 1);
                p1 += __shfl_xor_sync(0xFFFFFFFFu, p1, 2);
                if (tig == 0) {
                    kxb[(mt * 16 + g) * 33 + 32] = p0;
                    kxb[(mt * 16 + g + 8) * 33 + 32] = p1;
                }
            }
        }
        __syncthreads();

        if (tid < TROWS) {
            float s = b2[0];
            #pragma unroll
            for (int n4 = 0; n4 < 4; n4++) s += kx[n4 * KXNG + tid * 33 + 32];
            int op = tile * TROWS + tid;
            bool valid = (op < N);
            float sv = valid ? s : -FLT_MAX;

            float tmax = sv;
            #pragma unroll
            for (int off = 16; off > 0; off >>= 1)
                tmax = fmaxf(tmax, __shfl_xor_sync(0xFFFFFFFFu, tmax, off));
            wBest = fmaxf(wBest, tmax);

            if (valid) {
                d_scores[op] = s;
                if (s >= wBest - 1e-3f) {
                    int p = atomicAdd(&d_candCount, 1);
                    if (p < CANDCAP) { d_candList[p] = op; d_candScore[p] = s; }
                }
                if (s > tBest || (s == tBest && op < tArg)) { tBest = s; tArg = op; }
                if (s > mloc) {
                    float f = expf(mloc - s);
                    ssL = f * ssL + (mloc - s) * f * seL;
                    seL = f * seL + 1.f;
                    mloc = s;
                } else {
                    float e = expf(s - mloc);
                    seL += e;
                    ssL = fmaf(s - mloc, e, ssL);
                }
            }
        }
        __syncthreads();
    }

    if (tid < 32) {
        #pragma unroll
        for (int off = 16; off > 0; off >>= 1) {
            float ov = __shfl_xor_sync(0xFFFFFFFFu, tBest, off);
            int   oi = __shfl_xor_sync(0xFFFFFFFFu, tArg, off);
            if (ov > tBest || (ov == tBest && oi < tArg)) { tBest = ov; tArg = oi; }
            float om = __shfl_xor_sync(0xFFFFFFFFu, mloc, off);
            float oe = __shfl_xor_sync(0xFFFFFFFFu, seL, off);
            float os = __shfl_xor_sync(0xFFFFFFFFu, ssL, off);
            smx_merge(mloc, seL, ssL, om, oe, os);
        }
        if (lane == 0) {
            d_bMax[blockIdx.x] = tBest;
            d_bArg[blockIdx.x] = tArg;
            d_bM[blockIdx.x] = mloc;
            d_bE[blockIdx.x] = seL;
            d_bS[blockIdx.x] = ssL;
        }
    }
}

// ---------------- fused combine + refine + finalize (W1 staged in SMEM) ----------------
__global__ void combine_refine(const int* __restrict__ m_ids,
                               const int* __restrict__ job_idx,
                               const float* __restrict__ W1,
                               const float* __restrict__ b1,
                               const float* __restrict__ W2,
                               const float* __restrict__ b2,
                               float* __restrict__ out, int nparts) {
    extern __shared__ float W1s[];     // 128x128 = 64 KB
    __shared__ float sv[256]; __shared__ int si[256];
    __shared__ float smm[256], sE[256], sS[256];
    __shared__ float gMaxS, gES, gSS;
    __shared__ int scnt;
    __shared__ int slist[64];
    __shared__ float h0[128];
    __shared__ float red[128];
    __shared__ float bestS;
    __shared__ int bestI;
    int tid = threadIdx.x;

    // stage W1 into SMEM (coalesced float4; overlaps with phase 0 below)
    {
        const float4* Wg = (const float4*)W1;
        float4* Ws4 = (float4*)W1s;
        for (int i = tid; i < 4096; i += 256) Ws4[i] = Wg[i];
    }

    // ---- phase 0: combine block partials ----
    float bv = -FLT_MAX; int bi = 0x7FFFFFFF;
    float m = -FLT_MAX, e = 0.f, s = 0.f;
    for (int i = tid; i < nparts; i += 256) {
        float v = d_bMax[i]; int ix = d_bArg[i];
        if (v > bv || (v == bv && ix < bi)) { bv = v; bi = ix; }
        smx_merge(m, e, s, d_bM[i], d_bE[i], d_bS[i]);
    }
    sv[tid] = bv; si[tid] = bi; smm[tid] = m; sE[tid] = e; sS[tid] = s;
    __syncthreads();
    for (int st = 128; st > 0; st >>= 1) {
        if (tid < st) {
            float v = sv[tid + st]; int ix = si[tid + st];
            if (v > sv[tid] || (v == sv[tid] && ix < si[tid])) { sv[tid] = v; si[tid] = ix; }
            float m1 = smm[tid], e1 = sE[tid], s1 = sS[tid];
            smx_merge(m1, e1, s1, smm[tid + st], sE[tid + st], sS[tid + st]);
            smm[tid] = m1; sE[tid] = e1; sS[tid] = s1;
        }
        __syncthreads();
    }
    if (tid == 0) {
        gMaxS = sv[0]; gES = sE[0]; gSS = sS[0];
        scnt = 0; bestS = -FLT_MAX; bestI = si[0];
    }
    __syncthreads();

    // ---- phase 1: coalesced filter of (candScore, candList) ----
    int cnt = d_candCount;
    if (cnt > CANDCAP) cnt = CANDCAP;
    float thr = gMaxS - 1e-3f;
    for (int c = tid; c < cnt; c += 256) {
        float sc = d_candScore[c];
        if (sc >= thr) {
            int p = atomicAdd(&scnt, 1);
            if (p < 64) slist[p] = d_candList[c];
        }
    }
    __syncthreads();
    int nfin = scnt; if (nfin > 64) nfin = 64;

    // ---- phase 2: exact fp32 rescoring (W1 from SMEM; ~0.3us per survivor) ----
    for (int c = 0; c < nfin; c++) {
        int op = slist[c];
        if (tid < 128) {
            int mm = m_ids[op], jj = job_idx[op];
            h0[tid] = fmaxf(d_Qm[mm * HDIM + tid] + d_Pj[jj * HDIM + tid], 0.f);
        }
        __syncthreads();
        if (tid < 128) {
            float a = b1[tid];
            #pragma unroll 8
            for (int k = 0; k < HDIM; k++)
                a = fmaf(h0[k], W1s[k * HDIM + tid], a);
            red[tid] = fmaxf(a, 0.f) * W2[tid];
        }
        __syncthreads();
        for (int st = 64; st > 0; st >>= 1) {
            if (tid < st && tid + st < 128) red[tid] += red[tid + st];
            __syncthreads();
        }
        if (tid == 0) {
            float sx = red[0] + b2[0];
            if (sx > bestS || (sx == bestS && op < bestI)) { bestS = sx; bestI = op; }
        }
        __syncthreads();
    }

    if (tid == 0) {
        float Z = gES, S = gSS;
        float mx = gMaxS;
        int arg = bestI;
        float logZ = logf(Z);
        float lp = (d_scores[arg] - mx) - logZ;
        out[0] = (float)arg;
        out[1] = expf(lp);
        out[2] = lp;
        out[3] = logZ - S / Z;
        d_candCount = 0;
    }
}

// ---------------- launch ----------------
extern "C" void kernel_launch(void* const* d_in, const int* in_sizes, int n_in,
                              void* d_out, int out_size) {
    const float* xg    = (const float*)d_in[0];
    const float* xm    = (const float*)d_in[1];
    const float* xjob  = (const float*)d_in[2];
    const int*   m_ids = (const int*)d_in[3];
    const int*   jidx  = (const int*)d_in[4];
    const float* W0    = (const float*)d_in[5];
    const float* b0    = (const float*)d_in[6];
    const float* W1    = (const float*)d_in[7];
    const float* b1    = (const float*)d_in[8];
    const float* W2    = (const float*)d_in[9];
    const float* b2    = (const float*)d_in[10];

    int M = in_sizes[1] / HDIM;
    int J = in_sizes[2] / HDIM;
    int N = in_sizes[3];

    const int SMEM_PRE = (16384 + PTR * 128) * 4;
    const int SMEM_CR  = 16384 * 4;       // 64 KB W1 stage
    cudaFuncSetAttribute(pre_kernel,     cudaFuncAttributeMaxDynamicSharedMemorySize, SMEM_PRE);
    cudaFuncSetAttribute(mma_main,       cudaFuncAttributeMaxDynamicSharedMemorySize, SMEM_MMA);
    cudaFuncSetAttribute(combine_refine, cudaFuncAttributeMaxDynamicSharedMemorySize, SMEM_CR);

    g0_kernel<<<1, 256>>>(xg, W0, b0);

    int gQm = (M + PTR - 1) / PTR;
    int gPj = (J + PTR - 1) / PTR;
    pre_kernel<<<gQm + gPj, 256, SMEM_PRE>>>(xm, xjob, W0, M, J, gQm);

    const int GRID_MAIN = 304;
    mma_main<<<GRID_MAIN, 256, SMEM_MMA>>>(m_ids, jidx, W1, b1, W2, b2, N);

    combine_refine<<<1, 256, SMEM_CR>>>(m_ids, jidx, W1, b1, W2, b2, (float*)d_out, GRID_MAIN);
}